// round 13
// baseline (speedup 1.0000x reference)
#include <cuda_runtime.h>
#include <math.h>
#include <stdint.h>

#define BB 4
#define LL 2048
#define IN_DIM 64
#define DM 256
#define DI 512
#define DS 16
#define DCONV 4
#define DTR 16
#define NLAYERS 4
#define BL (BB*LL)   // 8192 rows

// ---------------- scratch (static __device__, no allocation) ----------------
__device__ float g_h[BL*DM];
__device__ float g_xz[BL*2*DI];
__device__ float g_u[BL*DI];
__device__ float g_dt[BL*DTR];      // dt part of dbc (row-major, lda=16)
__device__ float g_bcT[32*BL];      // B rows 0-15, C rows 16-31, transposed [s][t]
__device__ float g_delta[BL*DI];    // softplus delta, row-major (R11 layout)
__device__ float g_y[BL*DI];
__device__ float g_ln[BL*DM];

// ---------------- helpers ----------------------------------------------------
__device__ __forceinline__ uint32_t smem_u32(const void* p) {
    uint32_t a;
    asm("{ .reg .u64 t; cvta.to.shared.u64 t, %1; cvt.u32.u64 %0, t; }"
        : "=r"(a) : "l"(p));
    return a;
}
__device__ __forceinline__ uint32_t f2tf32(float x) {
    uint32_t u;
    asm("cvt.rna.tf32.f32 %0, %1;" : "=r"(u) : "f"(x));
    return u;
}
__device__ __forceinline__ void mma16n8k8(float* d, const uint32_t* a, const uint32_t* b) {
    asm volatile(
        "mma.sync.aligned.m16n8k8.row.col.f32.tf32.tf32.f32 "
        "{%0,%1,%2,%3}, {%4,%5,%6,%7}, {%8,%9}, {%0,%1,%2,%3};"
        : "+f"(d[0]), "+f"(d[1]), "+f"(d[2]), "+f"(d[3])
        : "r"(a[0]), "r"(a[1]), "r"(a[2]), "r"(a[3]), "r"(b[0]), "r"(b[1]));
}
__device__ __forceinline__ void cp16(uint32_t dst, const float* src, int srcsize) {
    asm volatile("cp.async.ca.shared.global [%0], [%1], 16, %2;"
                 :: "r"(dst), "l"(src), "r"(srcsize) : "memory");
}
#define CP_COMMIT()  asm volatile("cp.async.commit_group;" ::: "memory")
#define CP_WAIT(n)   asm volatile("cp.async.wait_group %0;" :: "n"(n) : "memory")

// ================== split-tf32 tensor-core GEMM: C = A @ W^T =================
// act: 0 = plain (+bias/res), 1 = softplus,
//      2 = split store: gn<16 -> C[gm*16+gn] (dt), gn>=16 -> C2[(gn-16)*BL+gm] (bcT)
#define TSTR 20

template<int BMT, int NT>
__global__ __launch_bounds__(NT) void mma_gemm_t(
    const float* __restrict__ A, int lda,
    const float* __restrict__ W,
    const float* __restrict__ bias,
    const float* __restrict__ res,
    float* __restrict__ C,
    float* __restrict__ C2,
    int N, int K, int act)
{
    constexpr int APT = BMT * 4 / NT;
    constexpr int BPT = 64 * 4 / NT;

    __shared__ float sA[2][BMT*TSTR];
    __shared__ float sB[2][64*TSTR];

    int tid = threadIdx.x;
    int wid = tid >> 5, lid = tid & 31;
    int warp_m = wid >> 1;
    int warp_n = wid & 1;
    int bm = blockIdx.y * BMT;
    int bn = blockIdx.x * 64;

    uint32_t aBase = smem_u32(&sA[0][0]);
    uint32_t bBase = smem_u32(&sB[0][0]);
    const uint32_t A_STAGE = BMT*TSTR*4;
    const uint32_t B_STAGE = 64*TSTR*4;

    int arr[APT], ac4[APT];
    #pragma unroll
    for (int j = 0; j < APT; j++) {
        int e = tid + j*NT;
        arr[j] = e >> 2; ac4[j] = (e & 3) * 4;
    }
    int brr[BPT], bc4[BPT], bpred[BPT];
    const float* bsrc[BPT];
    #pragma unroll
    for (int j = 0; j < BPT; j++) {
        int e = tid + j*NT;
        brr[j] = e >> 2; bc4[j] = (e & 3) * 4;
        int gn = bn + brr[j];
        bpred[j] = (gn < N) ? 16 : 0;
        bsrc[j] = W + (size_t)((gn < N) ? gn : 0) * K;
    }

    float acc[2][4][4];
    #pragma unroll
    for (int i = 0; i < 2; i++)
        #pragma unroll
        for (int j = 0; j < 4; j++)
            #pragma unroll
            for (int e = 0; e < 4; e++) acc[i][j][e] = 0.f;

    int nk = K >> 4;

    #pragma unroll
    for (int j = 0; j < APT; j++)
        cp16(aBase + (uint32_t)((arr[j]*TSTR + ac4[j])*4),
             A + (size_t)(bm + arr[j])*lda + ac4[j], 16);
    #pragma unroll
    for (int j = 0; j < BPT; j++)
        cp16(bBase + (uint32_t)((brr[j]*TSTR + bc4[j])*4), bsrc[j] + bc4[j], bpred[j]);
    CP_COMMIT();

    for (int kc = 0; kc < nk; kc++) {
        int cur = kc & 1;
        if (kc + 1 < nk) {
            int k0 = (kc + 1) << 4;
            uint32_t so = (uint32_t)((kc + 1) & 1);
            #pragma unroll
            for (int j = 0; j < APT; j++)
                cp16(aBase + so*A_STAGE + (uint32_t)((arr[j]*TSTR + ac4[j])*4),
                     A + (size_t)(bm + arr[j])*lda + k0 + ac4[j], 16);
            #pragma unroll
            for (int j = 0; j < BPT; j++)
                cp16(bBase + so*B_STAGE + (uint32_t)((brr[j]*TSTR + bc4[j])*4),
                     bsrc[j] + k0 + bc4[j], bpred[j]);
            CP_COMMIT();
            CP_WAIT(1);
        } else {
            CP_WAIT(0);
        }
        __syncthreads();

        const float* cA = sA[cur];
        const float* cB = sB[cur];

        #pragma unroll
        for (int ks = 0; ks < 2; ks++) {
            int kk = ks * 8;
            uint32_t ah[2][4], al[2][4];
            {
                int r0 = warp_m*32 + (lid >> 2);
                int c0 = kk + (lid & 3);
                #pragma unroll
                for (int im = 0; im < 2; im++) {
                    const float* pa = cA + (r0 + im*16)*TSTR + c0;
                    float f0 = pa[0], f1 = pa[8*TSTR], f2 = pa[4], f3 = pa[8*TSTR + 4];
                    ah[im][0] = f2tf32(f0); al[im][0] = f2tf32(f0 - __uint_as_float(ah[im][0]));
                    ah[im][1] = f2tf32(f1); al[im][1] = f2tf32(f1 - __uint_as_float(ah[im][1]));
                    ah[im][2] = f2tf32(f2); al[im][2] = f2tf32(f2 - __uint_as_float(ah[im][2]));
                    ah[im][3] = f2tf32(f3); al[im][3] = f2tf32(f3 - __uint_as_float(ah[im][3]));
                }
            }
            uint32_t bh[4][2], bl[4][2];
            {
                int n0 = warp_n*32 + (lid >> 2);
                int c0 = kk + (lid & 3);
                #pragma unroll
                for (int jn = 0; jn < 4; jn++) {
                    const float* pb = cB + (n0 + jn*8)*TSTR + c0;
                    float f0 = pb[0], f1 = pb[4];
                    bh[jn][0] = f2tf32(f0); bl[jn][0] = f2tf32(f0 - __uint_as_float(bh[jn][0]));
                    bh[jn][1] = f2tf32(f1); bl[jn][1] = f2tf32(f1 - __uint_as_float(bh[jn][1]));
                }
            }
            #pragma unroll
            for (int im = 0; im < 2; im++)
                #pragma unroll
                for (int jn = 0; jn < 4; jn++) {
                    mma16n8k8(acc[im][jn], ah[im], bh[jn]);
                    mma16n8k8(acc[im][jn], al[im], bh[jn]);
                    mma16n8k8(acc[im][jn], ah[im], bl[jn]);
                }
        }
        __syncthreads();
    }

    // ---- epilogue ----
    int gm0 = bm + warp_m*32 + (lid >> 2);
    int gnb = bn + warp_n*32 + 2*(lid & 3);
    #pragma unroll
    for (int im = 0; im < 2; im++) {
        #pragma unroll
        for (int jn = 0; jn < 4; jn++) {
            int gn = gnb + jn*8;
            if (gn < N) {
                float b0 = 0.f, b1 = 0.f;
                if (bias) { b0 = bias[gn]; b1 = bias[gn+1]; }
                #pragma unroll
                for (int half = 0; half < 2; half++) {
                    int gm = gm0 + im*16 + half*8;
                    float v0 = acc[im][jn][half*2+0] + b0;
                    float v1 = acc[im][jn][half*2+1] + b1;
                    if (act == 1) {   // softplus
                        v0 = (v0 > 15.f) ? v0 : log1pf(__expf(v0));
                        v1 = (v1 > 15.f) ? v1 : log1pf(__expf(v1));
                    }
                    if (act == 2) {
                        if (gn < 16) {
                            C[(size_t)gm*16 + gn]     = v0;
                            C[(size_t)gm*16 + gn + 1] = v1;
                        } else {
                            C2[(size_t)(gn-16)*BL + gm] = v0;
                            C2[(size_t)(gn-15)*BL + gm] = v1;
                        }
                    } else {
                        if (res) {
                            float2 rv = *(const float2*)(res + (size_t)gm*N + gn);
                            v0 += rv.x; v1 += rv.y;
                        }
                        *(float2*)(C + (size_t)gm*N + gn) = make_float2(v0, v1);
                    }
                }
            }
        }
    }
}

// ---------------- depthwise causal conv (width 4) + SiLU --------------------
__global__ void conv_silu_kernel(const float* __restrict__ xz,
                                 const float* __restrict__ convw,
                                 const float* __restrict__ convb,
                                 float* __restrict__ u)
{
    int idx = blockIdx.x * blockDim.x + threadIdx.x;
    if (idx >= BL*DI) return;
    int d  = idx & (DI-1);
    int bt = idx >> 9;
    int t  = bt & (LL-1);

    float acc = convb[d];
    #pragma unroll
    for (int k = 0; k < DCONV; k++) {
        int tt = t - (DCONV-1) + k;
        if (tt >= 0)
            acc = fmaf(xz[(size_t)(bt - (DCONV-1) + k)*(2*DI) + d],
                       convw[d*DCONV + k], acc);
    }
    float sig = 1.f / (1.f + __expf(-acc));
    u[idx] = acc * sig;
}

// ====== chunked selective scan v5: float4 B/C from bcT, R11 semantics ========
__global__ __launch_bounds__(256) void scan5_kernel(
    const float* __restrict__ xz,
    const float* __restrict__ u_arr,
    const float* __restrict__ bcT,      // [32][BL]: B rows 0-15, C rows 16-31
    const float* __restrict__ delta_arr,// [BL][DI] row-major
    const float* __restrict__ a_log,
    const float* __restrict__ dparam,
    float* __restrict__ y_arr)
{
    __shared__ float s_delta[LL];
    __shared__ float s_u[LL];
    __shared__ float sC[16][17];
    __shared__ float sP[16][17];

    int bd = blockIdx.x;
    int d = bd & (DI-1), b = bd >> 9;
    int tid = threadIdx.x;
    int s = tid & 15, ck = tid >> 4;
    int t0 = ck * 128;
    int base = b * LL;

    float A = -__expf(a_log[d*DS + s]);
    const float* Brow = bcT + (size_t)s*BL + base + t0;
    const float* Crow = bcT + (size_t)(16 + s)*BL + base + t0;

    // ---- pass 1: chunk-local scan from h=0 (delta/u broadcast, B float4) ----
    float hloc = 0.f, sd = 0.f;
    for (int i4 = 0; i4 < 32; i4++) {
        float4 Bv = *(const float4*)(Brow + i4*4);
        #pragma unroll
        for (int j = 0; j < 4; j++) {
            int t = t0 + i4*4 + j;
            int row = base + t;
            float delta = delta_arr[(size_t)row*DI + d];
            float uu    = u_arr[(size_t)row*DI + d];
            hloc = fmaf(__expf(delta * A), hloc, delta * uu * (&Bv.x)[j]);
            sd += delta;
            if (s == 0) { s_delta[t] = delta; s_u[t] = uu; }
        }
    }
    sC[ck][s] = hloc;
    sP[ck][s] = __expf(sd * A);
    __syncthreads();

    // ---- prefix over chunks ----
    if (tid < 16) {
        float h = 0.f;
        #pragma unroll
        for (int c = 0; c < 16; c++) {
            float nh = fmaf(sP[c][tid], h, sC[c][tid]);
            sC[c][tid] = h;
            h = nh;
        }
    }
    __syncthreads();

    // ---- pass 2: rescan with true h_start, emit gated y ----
    float h = sC[ck][s];
    float Dp = dparam[d];
    for (int i4 = 0; i4 < 32; i4++) {
        float4 Bv = *(const float4*)(Brow + i4*4);
        float4 Cv = *(const float4*)(Crow + i4*4);
        #pragma unroll
        for (int j = 0; j < 4; j++) {
            int t = t0 + i4*4 + j;
            int row = base + t;
            float delta = s_delta[t];
            float uu    = s_u[t];
            h = fmaf(__expf(delta * A), h, delta * uu * (&Bv.x)[j]);

            float p = h * (&Cv.x)[j];
            p += __shfl_xor_sync(0xffffffffu, p, 8);
            p += __shfl_xor_sync(0xffffffffu, p, 4);
            p += __shfl_xor_sync(0xffffffffu, p, 2);
            p += __shfl_xor_sync(0xffffffffu, p, 1);

            if (s == 0) {
                float z = xz[(size_t)row*(2*DI) + DI + d];
                float sig = 1.f / (1.f + __expf(-z));
                y_arr[(size_t)row*DI + d] = (p + uu * Dp) * (z * sig);
            }
        }
    }
}

// ---------------- layernorm over 256 features (one warp per row) ------------
__global__ void ln_kernel(const float* __restrict__ x,
                          const float* __restrict__ w,
                          const float* __restrict__ b,
                          float* __restrict__ out)
{
    int warp = (blockIdx.x * blockDim.x + threadIdx.x) >> 5;
    int lane = threadIdx.x & 31;
    if (warp >= BL) return;
    const float* row = x + (size_t)warp*DM;

    float v[8];
    float sum = 0.f, sq = 0.f;
    #pragma unroll
    for (int k = 0; k < 8; k++) {
        v[k] = row[lane + k*32];
        sum += v[k];
        sq = fmaf(v[k], v[k], sq);
    }
    #pragma unroll
    for (int o = 16; o; o >>= 1) {
        sum += __shfl_xor_sync(0xffffffffu, sum, o);
        sq  += __shfl_xor_sync(0xffffffffu, sq,  o);
    }
    float mu  = sum * (1.f/DM);
    float var = sq * (1.f/DM) - mu*mu;
    float inv = rsqrtf(var + 1e-5f);
    #pragma unroll
    for (int k = 0; k < 8; k++) {
        int c = lane + k*32;
        out[(size_t)warp*DM + c] = (v[k]-mu)*inv*w[c] + b[c];
    }
}

// ---------------- host orchestration ----------------------------------------
static inline void launch_gemm_big(const float* A, int lda, const float* W,
                                   const float* bias, const float* res,
                                   float* C, float* C2, int N, int K, int act)
{
    dim3 grid((N + 63) / 64, BL / 128);
    mma_gemm_t<128, 256><<<grid, 256>>>(A, lda, W, bias, res, C, C2, N, K, act);
}
static inline void launch_gemm_small(const float* A, int lda, const float* W,
                                     const float* bias, const float* res,
                                     float* C, float* C2, int N, int K, int act)
{
    dim3 grid((N + 63) / 64, BL / 64);
    mma_gemm_t<64, 128><<<grid, 128>>>(A, lda, W, bias, res, C, C2, N, K, act);
}

extern "C" void kernel_launch(void* const* d_in, const int* in_sizes, int n_in,
                              void* d_out, int out_size)
{
    const float* x          = (const float*)d_in[0];
    const float* in_proj_w  = (const float*)d_in[1];
    const float* in_proj_b  = (const float*)d_in[2];
    const float* out_proj_w = (const float*)d_in[3];
    const float* out_proj_b = (const float*)d_in[4];
    const float* inw        = (const float*)d_in[5];
    const float* convw      = (const float*)d_in[6];
    const float* convb      = (const float*)d_in[7];
    const float* xpw        = (const float*)d_in[8];
    const float* dtw        = (const float*)d_in[9];
    const float* dtb        = (const float*)d_in[10];
    const float* a_log      = (const float*)d_in[11];
    const float* dparam     = (const float*)d_in[12];
    const float* outw       = (const float*)d_in[13];
    const float* lnw        = (const float*)d_in[14];
    const float* lnb        = (const float*)d_in[15];
    float* out = (float*)d_out;

    float *h, *xz, *u, *dt, *bcT, *delta, *y, *ln;
    cudaGetSymbolAddress((void**)&h,     g_h);
    cudaGetSymbolAddress((void**)&xz,    g_xz);
    cudaGetSymbolAddress((void**)&u,     g_u);
    cudaGetSymbolAddress((void**)&dt,    g_dt);
    cudaGetSymbolAddress((void**)&bcT,   g_bcT);
    cudaGetSymbolAddress((void**)&delta, g_delta);
    cudaGetSymbolAddress((void**)&y,     g_y);
    cudaGetSymbolAddress((void**)&ln,    g_ln);

    // h = x @ in_proj_w^T + in_proj_b
    launch_gemm_big(x, IN_DIM, in_proj_w, in_proj_b, nullptr, h, nullptr,
                    DM, IN_DIM, 0);

    for (int l = 0; l < NLAYERS; l++) {
        // xz = h @ inw[l]^T
        launch_gemm_big(h, DM, inw + (size_t)l*2*DI*DM, nullptr, nullptr,
                        xz, nullptr, 2*DI, DM, 0);
        // u = silu(causal_conv(xz[:, :DI]))
        conv_silu_kernel<<<(BL*DI)/256, 256>>>(xz, convw + l*DI*DCONV, convb + l*DI, u);
        // dbc = u @ xpw[l]^T -> dt row-major + B/C transposed (verified cost-neutral)
        launch_gemm_small(u, DI, xpw + (size_t)l*48*DI, nullptr, nullptr,
                          dt, bcT, 48, DI, 2);
        // delta = softplus(dt @ dtw[l]^T + dtb[l]) row-major (R11 layout)
        launch_gemm_big(dt, 16, dtw + (size_t)l*DI*DTR, dtb + l*DI, nullptr,
                        delta, nullptr, DI, DTR, 1);
        // chunked selective scan + gating (float4 B/C)
        scan5_kernel<<<BB*DI, 256>>>(xz, u, bcT, delta,
                                     a_log + (size_t)l*DI*DS, dparam + l*DI, y);
        // ln_in = y @ outw[l]^T + residual(h)
        launch_gemm_big(y, DI, outw + (size_t)l*DM*DI, nullptr, h,
                        ln, nullptr, DM, DI, 0);
        // h = layernorm(ln_in)
        ln_kernel<<<BL/8, 256>>>(ln, lnw + l*DM, lnb + l*DM, h);
    }

    // out = h @ out_proj_w^T + out_proj_b
    launch_gemm_big(h, DM, out_proj_w, out_proj_b, nullptr, out, nullptr,
                    DM, DM, 0);
}

// round 14
// speedup vs baseline: 1.2826x; 1.2826x over previous
#include <cuda_runtime.h>
#include <math.h>
#include <stdint.h>

#define BB 4
#define LL 2048
#define IN_DIM 64
#define DM 256
#define DI 512
#define DS 16
#define DCONV 4
#define DTR 16
#define NLAYERS 4
#define BL (BB*LL)   // 8192 rows

// ---------------- scratch (static __device__, no allocation) ----------------
__device__ float g_h[BL*DM];
__device__ float g_xz[BL*2*DI];
__device__ float g_u[BL*DI];
__device__ float g_dbc[BL*48];
__device__ float g_delta[BL*DI];
__device__ float g_y[BL*DI];
__device__ float g_ln[BL*DM];

// ---------------- helpers ----------------------------------------------------
__device__ __forceinline__ uint32_t smem_u32(const void* p) {
    uint32_t a;
    asm("{ .reg .u64 t; cvta.to.shared.u64 t, %1; cvt.u32.u64 %0, t; }"
        : "=r"(a) : "l"(p));
    return a;
}
__device__ __forceinline__ uint32_t f2tf32(float x) {
    uint32_t u;
    asm("cvt.rna.tf32.f32 %0, %1;" : "=r"(u) : "f"(x));
    return u;
}
__device__ __forceinline__ void mma16n8k8(float* d, const uint32_t* a, const uint32_t* b) {
    asm volatile(
        "mma.sync.aligned.m16n8k8.row.col.f32.tf32.tf32.f32 "
        "{%0,%1,%2,%3}, {%4,%5,%6,%7}, {%8,%9}, {%0,%1,%2,%3};"
        : "+f"(d[0]), "+f"(d[1]), "+f"(d[2]), "+f"(d[3])
        : "r"(a[0]), "r"(a[1]), "r"(a[2]), "r"(a[3]), "r"(b[0]), "r"(b[1]));
}
__device__ __forceinline__ void cp16(uint32_t dst, const float* src, int srcsize) {
    asm volatile("cp.async.ca.shared.global [%0], [%1], 16, %2;"
                 :: "r"(dst), "l"(src), "r"(srcsize) : "memory");
}
#define CP_COMMIT()  asm volatile("cp.async.commit_group;" ::: "memory")
#define CP_WAIT(n)   asm volatile("cp.async.wait_group %0;" :: "n"(n) : "memory")

// ================== split-tf32 tensor-core GEMM: C = A @ W^T =================
// Template on (BMT, NT): BMT x 64 tile, NT threads, warp tile 32x32.
// BK=16, cp.async double-buffered smem (R5/R11-proven structure).
#define TSTR 20   // smem row stride in words (conflict-free)

template<int BMT, int NT>
__global__ __launch_bounds__(NT) void mma_gemm_t(
    const float* __restrict__ A, int lda,
    const float* __restrict__ W,
    const float* __restrict__ bias,
    const float* __restrict__ res,
    float* __restrict__ C,
    int N, int K, int act)
{
    constexpr int APT = BMT * 4 / NT;
    constexpr int BPT = 64 * 4 / NT;

    __shared__ float sA[2][BMT*TSTR];
    __shared__ float sB[2][64*TSTR];

    int tid = threadIdx.x;
    int wid = tid >> 5, lid = tid & 31;
    int warp_m = wid >> 1;
    int warp_n = wid & 1;
    int bm = blockIdx.y * BMT;
    int bn = blockIdx.x * 64;

    uint32_t aBase = smem_u32(&sA[0][0]);
    uint32_t bBase = smem_u32(&sB[0][0]);
    const uint32_t A_STAGE = BMT*TSTR*4;
    const uint32_t B_STAGE = 64*TSTR*4;

    int arr[APT], ac4[APT];
    #pragma unroll
    for (int j = 0; j < APT; j++) {
        int e = tid + j*NT;
        arr[j] = e >> 2; ac4[j] = (e & 3) * 4;
    }
    int brr[BPT], bc4[BPT], bpred[BPT];
    const float* bsrc[BPT];
    #pragma unroll
    for (int j = 0; j < BPT; j++) {
        int e = tid + j*NT;
        brr[j] = e >> 2; bc4[j] = (e & 3) * 4;
        int gn = bn + brr[j];
        bpred[j] = (gn < N) ? 16 : 0;
        bsrc[j] = W + (size_t)((gn < N) ? gn : 0) * K;
    }

    float acc[2][4][4];
    #pragma unroll
    for (int i = 0; i < 2; i++)
        #pragma unroll
        for (int j = 0; j < 4; j++)
            #pragma unroll
            for (int e = 0; e < 4; e++) acc[i][j][e] = 0.f;

    int nk = K >> 4;

    #pragma unroll
    for (int j = 0; j < APT; j++)
        cp16(aBase + (uint32_t)((arr[j]*TSTR + ac4[j])*4),
             A + (size_t)(bm + arr[j])*lda + ac4[j], 16);
    #pragma unroll
    for (int j = 0; j < BPT; j++)
        cp16(bBase + (uint32_t)((brr[j]*TSTR + bc4[j])*4), bsrc[j] + bc4[j], bpred[j]);
    CP_COMMIT();

    for (int kc = 0; kc < nk; kc++) {
        int cur = kc & 1;
        if (kc + 1 < nk) {
            int k0 = (kc + 1) << 4;
            uint32_t so = (uint32_t)((kc + 1) & 1);
            #pragma unroll
            for (int j = 0; j < APT; j++)
                cp16(aBase + so*A_STAGE + (uint32_t)((arr[j]*TSTR + ac4[j])*4),
                     A + (size_t)(bm + arr[j])*lda + k0 + ac4[j], 16);
            #pragma unroll
            for (int j = 0; j < BPT; j++)
                cp16(bBase + so*B_STAGE + (uint32_t)((brr[j]*TSTR + bc4[j])*4),
                     bsrc[j] + k0 + bc4[j], bpred[j]);
            CP_COMMIT();
            CP_WAIT(1);
        } else {
            CP_WAIT(0);
        }
        __syncthreads();

        const float* cA = sA[cur];
        const float* cB = sB[cur];

        #pragma unroll
        for (int ks = 0; ks < 2; ks++) {
            int kk = ks * 8;
            uint32_t ah[2][4], al[2][4];
            {
                int r0 = warp_m*32 + (lid >> 2);
                int c0 = kk + (lid & 3);
                #pragma unroll
                for (int im = 0; im < 2; im++) {
                    const float* pa = cA + (r0 + im*16)*TSTR + c0;
                    float f0 = pa[0], f1 = pa[8*TSTR], f2 = pa[4], f3 = pa[8*TSTR + 4];
                    ah[im][0] = f2tf32(f0); al[im][0] = f2tf32(f0 - __uint_as_float(ah[im][0]));
                    ah[im][1] = f2tf32(f1); al[im][1] = f2tf32(f1 - __uint_as_float(ah[im][1]));
                    ah[im][2] = f2tf32(f2); al[im][2] = f2tf32(f2 - __uint_as_float(ah[im][2]));
                    ah[im][3] = f2tf32(f3); al[im][3] = f2tf32(f3 - __uint_as_float(ah[im][3]));
                }
            }
            uint32_t bh[4][2], bl[4][2];
            {
                int n0 = warp_n*32 + (lid >> 2);
                int c0 = kk + (lid & 3);
                #pragma unroll
                for (int jn = 0; jn < 4; jn++) {
                    const float* pb = cB + (n0 + jn*8)*TSTR + c0;
                    float f0 = pb[0], f1 = pb[4];
                    bh[jn][0] = f2tf32(f0); bl[jn][0] = f2tf32(f0 - __uint_as_float(bh[jn][0]));
                    bh[jn][1] = f2tf32(f1); bl[jn][1] = f2tf32(f1 - __uint_as_float(bh[jn][1]));
                }
            }
            #pragma unroll
            for (int im = 0; im < 2; im++)
                #pragma unroll
                for (int jn = 0; jn < 4; jn++) {
                    mma16n8k8(acc[im][jn], ah[im], bh[jn]);
                    mma16n8k8(acc[im][jn], al[im], bh[jn]);
                    mma16n8k8(acc[im][jn], ah[im], bl[jn]);
                }
        }
        __syncthreads();
    }

    // ---- epilogue ----
    int gm0 = bm + warp_m*32 + (lid >> 2);
    int gnb = bn + warp_n*32 + 2*(lid & 3);
    #pragma unroll
    for (int im = 0; im < 2; im++) {
        #pragma unroll
        for (int jn = 0; jn < 4; jn++) {
            int gn = gnb + jn*8;
            if (gn < N) {
                float b0 = 0.f, b1 = 0.f;
                if (bias) { b0 = bias[gn]; b1 = bias[gn+1]; }
                #pragma unroll
                for (int half = 0; half < 2; half++) {
                    int gm = gm0 + im*16 + half*8;
                    float v0 = acc[im][jn][half*2+0] + b0;
                    float v1 = acc[im][jn][half*2+1] + b1;
                    if (act == 1) {
                        v0 = (v0 > 15.f) ? v0 : log1pf(__expf(v0));
                        v1 = (v1 > 15.f) ? v1 : log1pf(__expf(v1));
                    }
                    if (res) {
                        float2 rv = *(const float2*)(res + (size_t)gm*N + gn);
                        v0 += rv.x; v1 += rv.y;
                    }
                    *(float2*)(C + (size_t)gm*N + gn) = make_float2(v0, v1);
                }
            }
        }
    }
}

// ---------------- depthwise causal conv (width 4) + SiLU --------------------
__global__ void conv_silu_kernel(const float* __restrict__ xz,
                                 const float* __restrict__ convw,
                                 const float* __restrict__ convb,
                                 float* __restrict__ u)
{
    int idx = blockIdx.x * blockDim.x + threadIdx.x;
    if (idx >= BL*DI) return;
    int d  = idx & (DI-1);
    int bt = idx >> 9;
    int t  = bt & (LL-1);

    float acc = convb[d];
    #pragma unroll
    for (int k = 0; k < DCONV; k++) {
        int tt = t - (DCONV-1) + k;
        if (tt >= 0)
            acc = fmaf(xz[(size_t)(bt - (DCONV-1) + k)*(2*DI) + d],
                       convw[d*DCONV + k], acc);
    }
    float sig = 1.f / (1.f + __expf(-acc));
    u[idx] = acc * sig;
}

// ====== chunked selective scan: block per (b,d), 32 chunks x 64 t ============
// Identical arithmetic + access patterns to R11 scan2; only more parallel.
__global__ __launch_bounds__(512) void scan2_kernel(
    const float* __restrict__ xz,
    const float* __restrict__ u_arr,
    const float* __restrict__ dbc,
    const float* __restrict__ delta_arr,
    const float* __restrict__ a_log,
    const float* __restrict__ dparam,
    float* __restrict__ y_arr)
{
    __shared__ float s_delta[LL];
    __shared__ float s_u[LL];
    __shared__ float sC[32][17];
    __shared__ float sP[32][17];

    int bd = blockIdx.x;
    int d = bd & (DI-1), b = bd >> 9;
    int tid = threadIdx.x;
    int s = tid & 15, ck = tid >> 4;    // 32 chunks
    int t0 = ck * 64;
    int base = b * LL;

    float A = -__expf(a_log[d*DS + s]);

    // ---- pass 1: chunk-local scan from h=0 ----
    float hloc = 0.f, sd = 0.f;
    #pragma unroll 4
    for (int i = 0; i < 64; i++) {
        int t = t0 + i;
        int row = base + t;
        float delta = delta_arr[(size_t)row*DI + d];
        float uu    = u_arr[(size_t)row*DI + d];
        float Bt    = dbc[(size_t)row*48 + DTR + s];
        float dA = __expf(delta * A);
        hloc = fmaf(dA, hloc, delta * uu * Bt);
        sd += delta;
        if (s == 0) { s_delta[t] = delta; s_u[t] = uu; }
    }
    sC[ck][s] = hloc;
    sP[ck][s] = __expf(sd * A);
    __syncthreads();

    // ---- prefix over 32 chunks (16 threads, one per state) ----
    if (tid < 16) {
        float h = 0.f;
        #pragma unroll
        for (int c = 0; c < 32; c++) {
            float nh = fmaf(sP[c][tid], h, sC[c][tid]);
            sC[c][tid] = h;
            h = nh;
        }
    }
    __syncthreads();

    // ---- pass 2: rescan with true h_start, emit y ----
    float h = sC[ck][s];
    float Dp = dparam[d];
    #pragma unroll 4
    for (int i = 0; i < 64; i++) {
        int t = t0 + i;
        int row = base + t;
        float delta = s_delta[t];
        float uu    = s_u[t];
        float Bt    = dbc[(size_t)row*48 + DTR + s];
        float Ct    = dbc[(size_t)row*48 + DTR + DS + s];
        float dA = __expf(delta * A);
        h = fmaf(dA, h, delta * uu * Bt);

        float p = h * Ct;
        p += __shfl_xor_sync(0xffffffffu, p, 8);
        p += __shfl_xor_sync(0xffffffffu, p, 4);
        p += __shfl_xor_sync(0xffffffffu, p, 2);
        p += __shfl_xor_sync(0xffffffffu, p, 1);

        if (s == 0) {
            float z = xz[(size_t)row*(2*DI) + DI + d];
            float sig = 1.f / (1.f + __expf(-z));
            y_arr[(size_t)row*DI + d] = (p + uu * Dp) * (z * sig);
        }
    }
}

// ---------------- layernorm over 256 features (one warp per row) ------------
__global__ void ln_kernel(const float* __restrict__ x,
                          const float* __restrict__ w,
                          const float* __restrict__ b,
                          float* __restrict__ out)
{
    int warp = (blockIdx.x * blockDim.x + threadIdx.x) >> 5;
    int lane = threadIdx.x & 31;
    if (warp >= BL) return;
    const float* row = x + (size_t)warp*DM;

    float v[8];
    float sum = 0.f, sq = 0.f;
    #pragma unroll
    for (int k = 0; k < 8; k++) {
        v[k] = row[lane + k*32];
        sum += v[k];
        sq = fmaf(v[k], v[k], sq);
    }
    #pragma unroll
    for (int o = 16; o; o >>= 1) {
        sum += __shfl_xor_sync(0xffffffffu, sum, o);
        sq  += __shfl_xor_sync(0xffffffffu, sq,  o);
    }
    float mu  = sum * (1.f/DM);
    float var = sq * (1.f/DM) - mu*mu;
    float inv = rsqrtf(var + 1e-5f);
    #pragma unroll
    for (int k = 0; k < 8; k++) {
        int c = lane + k*32;
        out[(size_t)warp*DM + c] = (v[k]-mu)*inv*w[c] + b[c];
    }
}

// ---------------- host orchestration ----------------------------------------
static inline void launch_gemm_big(const float* A, int lda, const float* W,
                                   const float* bias, const float* res,
                                   float* C, int N, int K, int act)
{
    dim3 grid((N + 63) / 64, BL / 128);
    mma_gemm_t<128, 256><<<grid, 256>>>(A, lda, W, bias, res, C, N, K, act);
}
static inline void launch_gemm_small(const float* A, int lda, const float* W,
                                     const float* bias, const float* res,
                                     float* C, int N, int K, int act)
{
    dim3 grid((N + 63) / 64, BL / 64);
    mma_gemm_t<64, 128><<<grid, 128>>>(A, lda, W, bias, res, C, N, K, act);
}

extern "C" void kernel_launch(void* const* d_in, const int* in_sizes, int n_in,
                              void* d_out, int out_size)
{
    const float* x          = (const float*)d_in[0];
    const float* in_proj_w  = (const float*)d_in[1];
    const float* in_proj_b  = (const float*)d_in[2];
    const float* out_proj_w = (const float*)d_in[3];
    const float* out_proj_b = (const float*)d_in[4];
    const float* inw        = (const float*)d_in[5];
    const float* convw      = (const float*)d_in[6];
    const float* convb      = (const float*)d_in[7];
    const float* xpw        = (const float*)d_in[8];
    const float* dtw        = (const float*)d_in[9];
    const float* dtb        = (const float*)d_in[10];
    const float* a_log      = (const float*)d_in[11];
    const float* dparam     = (const float*)d_in[12];
    const float* outw       = (const float*)d_in[13];
    const float* lnw        = (const float*)d_in[14];
    const float* lnb        = (const float*)d_in[15];
    float* out = (float*)d_out;

    // allow multiple GEMM blocks per SM (carveout hint; deterministic, graph-safe)
    cudaFuncSetAttribute(mma_gemm_t<128, 256>,
                         cudaFuncAttributePreferredSharedMemoryCarveout, 100);
    cudaFuncSetAttribute(mma_gemm_t<64, 128>,
                         cudaFuncAttributePreferredSharedMemoryCarveout, 100);
    cudaFuncSetAttribute(scan2_kernel,
                         cudaFuncAttributePreferredSharedMemoryCarveout, 100);

    float *h, *xz, *u, *dbc, *delta, *y, *ln;
    cudaGetSymbolAddress((void**)&h,     g_h);
    cudaGetSymbolAddress((void**)&xz,    g_xz);
    cudaGetSymbolAddress((void**)&u,     g_u);
    cudaGetSymbolAddress((void**)&dbc,   g_dbc);
    cudaGetSymbolAddress((void**)&delta, g_delta);
    cudaGetSymbolAddress((void**)&y,     g_y);
    cudaGetSymbolAddress((void**)&ln,    g_ln);

    // h = x @ in_proj_w^T + in_proj_b
    launch_gemm_big(x, IN_DIM, in_proj_w, in_proj_b, nullptr, h, DM, IN_DIM, 0);

    for (int l = 0; l < NLAYERS; l++) {
        // xz = h @ inw[l]^T
        launch_gemm_big(h, DM, inw + (size_t)l*2*DI*DM, nullptr, nullptr, xz, 2*DI, DM, 0);
        // u = silu(causal_conv(xz[:, :DI]))
        conv_silu_kernel<<<(BL*DI)/256, 256>>>(xz, convw + l*DI*DCONV, convb + l*DI, u);
        // dbc = u @ xpw[l]^T   (N=48, small tile; verified faster)
        launch_gemm_small(u, DI, xpw + (size_t)l*48*DI, nullptr, nullptr, dbc, 48, DI, 0);
        // delta = softplus(dt @ dtw[l]^T + dtb[l])
        launch_gemm_big(dbc, 48, dtw + (size_t)l*DI*DTR, dtb + l*DI, nullptr, delta, DI, DTR, 1);
        // chunked selective scan + gating (512 threads, 32 chunks)
        scan2_kernel<<<BB*DI, 512>>>(xz, u, dbc, delta,
                                     a_log + (size_t)l*DI*DS, dparam + l*DI, y);
        // ln_in = y @ outw[l]^T + residual(h)
        launch_gemm_big(y, DI, outw + (size_t)l*DM*DI, nullptr, h, ln, DM, DI, 0);
        // h = layernorm(ln_in)
        ln_kernel<<<BL/8, 256>>>(ln, lnw + l*DM, lnb + l*DM, h);
    }

    // out = h @ out_proj_w^T + out_proj_b
    launch_gemm_big(h, DM, out_proj_w, out_proj_b, nullptr, out, DM, DM, 0);
}

// round 15
// speedup vs baseline: 1.3392x; 1.0442x over previous
#include <cuda_runtime.h>
#include <math.h>
#include <stdint.h>

#define BB 4
#define LL 2048
#define IN_DIM 64
#define DM 256
#define DI 512
#define DS 16
#define DCONV 4
#define DTR 16
#define NLAYERS 4
#define BL (BB*LL)   // 8192 rows

// ---------------- scratch (static __device__, no allocation) ----------------
__device__ float g_h[BL*DM];
__device__ float g_xz[BL*2*DI];
__device__ float g_u[BL*DI];
__device__ float g_dbc[BL*48];
__device__ float g_delta[BL*DI];
__device__ float g_y[BL*DI];
__device__ float g_ln[BL*DM];

// ---------------- helpers ----------------------------------------------------
__device__ __forceinline__ uint32_t smem_u32(const void* p) {
    uint32_t a;
    asm("{ .reg .u64 t; cvta.to.shared.u64 t, %1; cvt.u32.u64 %0, t; }"
        : "=r"(a) : "l"(p));
    return a;
}
__device__ __forceinline__ uint32_t f2tf32(float x) {
    uint32_t u;
    asm("cvt.rna.tf32.f32 %0, %1;" : "=r"(u) : "f"(x));
    return u;
}
__device__ __forceinline__ void mma16n8k8(float* d, const uint32_t* a, const uint32_t* b) {
    asm volatile(
        "mma.sync.aligned.m16n8k8.row.col.f32.tf32.tf32.f32 "
        "{%0,%1,%2,%3}, {%4,%5,%6,%7}, {%8,%9}, {%0,%1,%2,%3};"
        : "+f"(d[0]), "+f"(d[1]), "+f"(d[2]), "+f"(d[3])
        : "r"(a[0]), "r"(a[1]), "r"(a[2]), "r"(a[3]), "r"(b[0]), "r"(b[1]));
}
__device__ __forceinline__ void cp16(uint32_t dst, const float* src, int srcsize) {
    asm volatile("cp.async.ca.shared.global [%0], [%1], 16, %2;"
                 :: "r"(dst), "l"(src), "r"(srcsize) : "memory");
}
#define CP_COMMIT()  asm volatile("cp.async.commit_group;" ::: "memory")
#define CP_WAIT(n)   asm volatile("cp.async.wait_group %0;" :: "n"(n) : "memory")

// ================== split-tf32 tensor-core GEMM: C = A @ W^T =================
// Template on (BMT, NT, STAGES): BMT x 64 tile, NT threads, warp tile 32x32.
// BK=16, STAGES-deep cp.async pipeline: load latency hidden across STAGES-1
// compute iterations; one __syncthreads per K-iteration.
#define TSTR 20   // smem row stride in words (conflict-free)

template<int BMT, int NT, int STAGES>
__global__ __launch_bounds__(NT) void mma_gemm_t(
    const float* __restrict__ A, int lda,
    const float* __restrict__ W,
    const float* __restrict__ bias,
    const float* __restrict__ res,
    float* __restrict__ C,
    int N, int K, int act)
{
    constexpr int APT = BMT * 4 / NT;
    constexpr int BPT = 64 * 4 / NT;

    __shared__ float sA[STAGES][BMT*TSTR];
    __shared__ float sB[STAGES][64*TSTR];

    int tid = threadIdx.x;
    int wid = tid >> 5, lid = tid & 31;
    int warp_m = wid >> 1;
    int warp_n = wid & 1;
    int bm = blockIdx.y * BMT;
    int bn = blockIdx.x * 64;

    uint32_t aBase = smem_u32(&sA[0][0]);
    uint32_t bBase = smem_u32(&sB[0][0]);
    const uint32_t A_STAGE = BMT*TSTR*4;
    const uint32_t B_STAGE = 64*TSTR*4;

    int arr[APT], ac4[APT];
    #pragma unroll
    for (int j = 0; j < APT; j++) {
        int e = tid + j*NT;
        arr[j] = e >> 2; ac4[j] = (e & 3) * 4;
    }
    int brr[BPT], bc4[BPT], bpred[BPT];
    const float* bsrc[BPT];
    #pragma unroll
    for (int j = 0; j < BPT; j++) {
        int e = tid + j*NT;
        brr[j] = e >> 2; bc4[j] = (e & 3) * 4;
        int gn = bn + brr[j];
        bpred[j] = (gn < N) ? 16 : 0;
        bsrc[j] = W + (size_t)((gn < N) ? gn : 0) * K;
    }

    float acc[2][4][4];
    #pragma unroll
    for (int i = 0; i < 2; i++)
        #pragma unroll
        for (int j = 0; j < 4; j++)
            #pragma unroll
            for (int e = 0; e < 4; e++) acc[i][j][e] = 0.f;

    int nk = K >> 4;

    // ---- prologue: prefetch stages 0..STAGES-2 (one commit group each) ----
    #pragma unroll
    for (int st = 0; st < STAGES-1; st++) {
        if (st < nk) {
            int k0 = st << 4;
            #pragma unroll
            for (int j = 0; j < APT; j++)
                cp16(aBase + (uint32_t)st*A_STAGE + (uint32_t)((arr[j]*TSTR + ac4[j])*4),
                     A + (size_t)(bm + arr[j])*lda + k0 + ac4[j], 16);
            #pragma unroll
            for (int j = 0; j < BPT; j++)
                cp16(bBase + (uint32_t)st*B_STAGE + (uint32_t)((brr[j]*TSTR + bc4[j])*4),
                     bsrc[j] + k0 + bc4[j], bpred[j]);
        }
        CP_COMMIT();
    }

    for (int kc = 0; kc < nk; kc++) {
        CP_WAIT(STAGES-2);      // group kc complete
        __syncthreads();        // all threads' waits done; prev compute finished

        // issue prefetch for kc+STAGES-1 (buffer (kc-1)%STAGES, now free)
        int nxt = kc + STAGES - 1;
        if (nxt < nk) {
            int k0 = nxt << 4;
            uint32_t so = (uint32_t)(nxt % STAGES);
            #pragma unroll
            for (int j = 0; j < APT; j++)
                cp16(aBase + so*A_STAGE + (uint32_t)((arr[j]*TSTR + ac4[j])*4),
                     A + (size_t)(bm + arr[j])*lda + k0 + ac4[j], 16);
            #pragma unroll
            for (int j = 0; j < BPT; j++)
                cp16(bBase + so*B_STAGE + (uint32_t)((brr[j]*TSTR + bc4[j])*4),
                     bsrc[j] + k0 + bc4[j], bpred[j]);
        }
        CP_COMMIT();

        const float* cA = sA[kc % STAGES];
        const float* cB = sB[kc % STAGES];

        #pragma unroll
        for (int ks = 0; ks < 2; ks++) {
            int kk = ks * 8;
            uint32_t ah[2][4], al[2][4];
            {
                int r0 = warp_m*32 + (lid >> 2);
                int c0 = kk + (lid & 3);
                #pragma unroll
                for (int im = 0; im < 2; im++) {
                    const float* pa = cA + (r0 + im*16)*TSTR + c0;
                    float f0 = pa[0], f1 = pa[8*TSTR], f2 = pa[4], f3 = pa[8*TSTR + 4];
                    ah[im][0] = f2tf32(f0); al[im][0] = f2tf32(f0 - __uint_as_float(ah[im][0]));
                    ah[im][1] = f2tf32(f1); al[im][1] = f2tf32(f1 - __uint_as_float(ah[im][1]));
                    ah[im][2] = f2tf32(f2); al[im][2] = f2tf32(f2 - __uint_as_float(ah[im][2]));
                    ah[im][3] = f2tf32(f3); al[im][3] = f2tf32(f3 - __uint_as_float(ah[im][3]));
                }
            }
            uint32_t bh[4][2], bl[4][2];
            {
                int n0 = warp_n*32 + (lid >> 2);
                int c0 = kk + (lid & 3);
                #pragma unroll
                for (int jn = 0; jn < 4; jn++) {
                    const float* pb = cB + (n0 + jn*8)*TSTR + c0;
                    float f0 = pb[0], f1 = pb[4];
                    bh[jn][0] = f2tf32(f0); bl[jn][0] = f2tf32(f0 - __uint_as_float(bh[jn][0]));
                    bh[jn][1] = f2tf32(f1); bl[jn][1] = f2tf32(f1 - __uint_as_float(bh[jn][1]));
                }
            }
            #pragma unroll
            for (int im = 0; im < 2; im++)
                #pragma unroll
                for (int jn = 0; jn < 4; jn++) {
                    mma16n8k8(acc[im][jn], ah[im], bh[jn]);
                    mma16n8k8(acc[im][jn], al[im], bh[jn]);
                    mma16n8k8(acc[im][jn], ah[im], bl[jn]);
                }
        }
        // no trailing sync: next iteration's wait+sync provides the barrier
    }

    // ---- epilogue ----
    int gm0 = bm + warp_m*32 + (lid >> 2);
    int gnb = bn + warp_n*32 + 2*(lid & 3);
    #pragma unroll
    for (int im = 0; im < 2; im++) {
        #pragma unroll
        for (int jn = 0; jn < 4; jn++) {
            int gn = gnb + jn*8;
            if (gn < N) {
                float b0 = 0.f, b1 = 0.f;
                if (bias) { b0 = bias[gn]; b1 = bias[gn+1]; }
                #pragma unroll
                for (int half = 0; half < 2; half++) {
                    int gm = gm0 + im*16 + half*8;
                    float v0 = acc[im][jn][half*2+0] + b0;
                    float v1 = acc[im][jn][half*2+1] + b1;
                    if (act == 1) {
                        v0 = (v0 > 15.f) ? v0 : log1pf(__expf(v0));
                        v1 = (v1 > 15.f) ? v1 : log1pf(__expf(v1));
                    }
                    if (res) {
                        float2 rv = *(const float2*)(res + (size_t)gm*N + gn);
                        v0 += rv.x; v1 += rv.y;
                    }
                    *(float2*)(C + (size_t)gm*N + gn) = make_float2(v0, v1);
                }
            }
        }
    }
}

// ---------------- depthwise causal conv (width 4) + SiLU --------------------
__global__ void conv_silu_kernel(const float* __restrict__ xz,
                                 const float* __restrict__ convw,
                                 const float* __restrict__ convb,
                                 float* __restrict__ u)
{
    int idx = blockIdx.x * blockDim.x + threadIdx.x;
    if (idx >= BL*DI) return;
    int d  = idx & (DI-1);
    int bt = idx >> 9;
    int t  = bt & (LL-1);

    float acc = convb[d];
    #pragma unroll
    for (int k = 0; k < DCONV; k++) {
        int tt = t - (DCONV-1) + k;
        if (tt >= 0)
            acc = fmaf(xz[(size_t)(bt - (DCONV-1) + k)*(2*DI) + d],
                       convw[d*DCONV + k], acc);
    }
    float sig = 1.f / (1.f + __expf(-acc));
    u[idx] = acc * sig;
}

// ============ chunked selective scan (R11-exact): block per (b,d) ============
__global__ __launch_bounds__(256) void scan2_kernel(
    const float* __restrict__ xz,
    const float* __restrict__ u_arr,
    const float* __restrict__ dbc,
    const float* __restrict__ delta_arr,
    const float* __restrict__ a_log,
    const float* __restrict__ dparam,
    float* __restrict__ y_arr)
{
    __shared__ float s_delta[LL];
    __shared__ float s_u[LL];
    __shared__ float sC[16][17];
    __shared__ float sP[16][17];

    int bd = blockIdx.x;
    int d = bd & (DI-1), b = bd >> 9;
    int tid = threadIdx.x;
    int s = tid & 15, ck = tid >> 4;
    int t0 = ck * 128;
    int base = b * LL;

    float A = -__expf(a_log[d*DS + s]);

    // ---- pass 1: chunk-local scan from h=0 ----
    float hloc = 0.f, sd = 0.f;
    #pragma unroll 4
    for (int i = 0; i < 128; i++) {
        int t = t0 + i;
        int row = base + t;
        float delta = delta_arr[(size_t)row*DI + d];
        float uu    = u_arr[(size_t)row*DI + d];
        float Bt    = dbc[(size_t)row*48 + DTR + s];
        float dA = __expf(delta * A);
        hloc = fmaf(dA, hloc, delta * uu * Bt);
        sd += delta;
        if (s == 0) { s_delta[t] = delta; s_u[t] = uu; }
    }
    sC[ck][s] = hloc;
    sP[ck][s] = __expf(sd * A);
    __syncthreads();

    // ---- prefix over chunks ----
    if (tid < 16) {
        float h = 0.f;
        #pragma unroll
        for (int c = 0; c < 16; c++) {
            float nh = fmaf(sP[c][tid], h, sC[c][tid]);
            sC[c][tid] = h;
            h = nh;
        }
    }
    __syncthreads();

    // ---- pass 2: rescan with true h_start, emit y ----
    float h = sC[ck][s];
    float Dp = dparam[d];
    #pragma unroll 4
    for (int i = 0; i < 128; i++) {
        int t = t0 + i;
        int row = base + t;
        float delta = s_delta[t];
        float uu    = s_u[t];
        float Bt    = dbc[(size_t)row*48 + DTR + s];
        float Ct    = dbc[(size_t)row*48 + DTR + DS + s];
        float dA = __expf(delta * A);
        h = fmaf(dA, h, delta * uu * Bt);

        float p = h * Ct;
        p += __shfl_xor_sync(0xffffffffu, p, 8);
        p += __shfl_xor_sync(0xffffffffu, p, 4);
        p += __shfl_xor_sync(0xffffffffu, p, 2);
        p += __shfl_xor_sync(0xffffffffu, p, 1);

        if (s == 0) {
            float z = xz[(size_t)row*(2*DI) + DI + d];
            float sig = 1.f / (1.f + __expf(-z));
            y_arr[(size_t)row*DI + d] = (p + uu * Dp) * (z * sig);
        }
    }
}

// ---------------- layernorm over 256 features (one warp per row) ------------
__global__ void ln_kernel(const float* __restrict__ x,
                          const float* __restrict__ w,
                          const float* __restrict__ b,
                          float* __restrict__ out)
{
    int warp = (blockIdx.x * blockDim.x + threadIdx.x) >> 5;
    int lane = threadIdx.x & 31;
    if (warp >= BL) return;
    const float* row = x + (size_t)warp*DM;

    float v[8];
    float sum = 0.f, sq = 0.f;
    #pragma unroll
    for (int k = 0; k < 8; k++) {
        v[k] = row[lane + k*32];
        sum += v[k];
        sq = fmaf(v[k], v[k], sq);
    }
    #pragma unroll
    for (int o = 16; o; o >>= 1) {
        sum += __shfl_xor_sync(0xffffffffu, sum, o);
        sq  += __shfl_xor_sync(0xffffffffu, sq,  o);
    }
    float mu  = sum * (1.f/DM);
    float var = sq * (1.f/DM) - mu*mu;
    float inv = rsqrtf(var + 1e-5f);
    #pragma unroll
    for (int k = 0; k < 8; k++) {
        int c = lane + k*32;
        out[(size_t)warp*DM + c] = (v[k]-mu)*inv*w[c] + b[c];
    }
}

// ---------------- host orchestration ----------------------------------------
static inline void launch_gemm_big(const float* A, int lda, const float* W,
                                   const float* bias, const float* res,
                                   float* C, int N, int K, int act)
{
    dim3 grid((N + 63) / 64, BL / 128);
    mma_gemm_t<128, 256, 3><<<grid, 256>>>(A, lda, W, bias, res, C, N, K, act);
}
static inline void launch_gemm_small(const float* A, int lda, const float* W,
                                     const float* bias, const float* res,
                                     float* C, int N, int K, int act)
{
    dim3 grid((N + 63) / 64, BL / 64);
    mma_gemm_t<64, 128, 4><<<grid, 128>>>(A, lda, W, bias, res, C, N, K, act);
}

extern "C" void kernel_launch(void* const* d_in, const int* in_sizes, int n_in,
                              void* d_out, int out_size)
{
    const float* x          = (const float*)d_in[0];
    const float* in_proj_w  = (const float*)d_in[1];
    const float* in_proj_b  = (const float*)d_in[2];
    const float* out_proj_w = (const float*)d_in[3];
    const float* out_proj_b = (const float*)d_in[4];
    const float* inw        = (const float*)d_in[5];
    const float* convw      = (const float*)d_in[6];
    const float* convb      = (const float*)d_in[7];
    const float* xpw        = (const float*)d_in[8];
    const float* dtw        = (const float*)d_in[9];
    const float* dtb        = (const float*)d_in[10];
    const float* a_log      = (const float*)d_in[11];
    const float* dparam     = (const float*)d_in[12];
    const float* outw       = (const float*)d_in[13];
    const float* lnw        = (const float*)d_in[14];
    const float* lnb        = (const float*)d_in[15];
    float* out = (float*)d_out;

    float *h, *xz, *u, *dbc, *delta, *y, *ln;
    cudaGetSymbolAddress((void**)&h,     g_h);
    cudaGetSymbolAddress((void**)&xz,    g_xz);
    cudaGetSymbolAddress((void**)&u,     g_u);
    cudaGetSymbolAddress((void**)&dbc,   g_dbc);
    cudaGetSymbolAddress((void**)&delta, g_delta);
    cudaGetSymbolAddress((void**)&y,     g_y);
    cudaGetSymbolAddress((void**)&ln,    g_ln);

    // h = x @ in_proj_w^T + in_proj_b
    launch_gemm_big(x, IN_DIM, in_proj_w, in_proj_b, nullptr, h, DM, IN_DIM, 0);

    for (int l = 0; l < NLAYERS; l++) {
        // xz = h @ inw[l]^T
        launch_gemm_big(h, DM, inw + (size_t)l*2*DI*DM, nullptr, nullptr, xz, 2*DI, DM, 0);
        // u = silu(causal_conv(xz[:, :DI]))
        conv_silu_kernel<<<(BL*DI)/256, 256>>>(xz, convw + l*DI*DCONV, convb + l*DI, u);
        // dbc = u @ xpw[l]^T   (N=48, small tile; verified faster)
        launch_gemm_small(u, DI, xpw + (size_t)l*48*DI, nullptr, nullptr, dbc, 48, DI, 0);
        // delta = softplus(dt @ dtw[l]^T + dtb[l])
        launch_gemm_big(dbc, 48, dtw + (size_t)l*DI*DTR, dtb + l*DI, nullptr, delta, DI, DTR, 1);
        // chunked selective scan + gating (R11-exact)
        scan2_kernel<<<BB*DI, 256>>>(xz, u, dbc, delta,
                                     a_log + (size_t)l*DI*DS, dparam + l*DI, y);
        // ln_in = y @ outw[l]^T + residual(h)
        launch_gemm_big(y, DI, outw + (size_t)l*DM*DI, nullptr, h, ln, DM, DI, 0);
        // h = layernorm(ln_in)
        ln_kernel<<<BL/8, 256>>>(ln, lnw + l*DM, lnb + l*DM, h);
    }

    // out = h @ out_proj_w^T + out_proj_b
    launch_gemm_big(h, DM, out_proj_w, out_proj_b, nullptr, out, DM, DM, 0);
}

// round 16
// speedup vs baseline: 1.3650x; 1.0192x over previous
#include <cuda_runtime.h>
#include <math.h>
#include <stdint.h>

#define BB 4
#define LL 2048
#define IN_DIM 64
#define DM 256
#define DI 512
#define DS 16
#define DCONV 4
#define DTR 16
#define NLAYERS 4
#define BL (BB*LL)   // 8192 rows

// ---------------- scratch (static __device__, no allocation) ----------------
__device__ float g_h[BL*DM];
__device__ float g_xz[BL*2*DI];
__device__ float g_u[BL*DI];
__device__ float g_dbc[BL*48];
__device__ float g_delta[BL*DI];
__device__ float g_uT[(size_t)DI*BL];      // u transposed [d][t]
__device__ float g_deltaT[(size_t)DI*BL];  // delta transposed [d][t]
__device__ float g_y[BL*DI];
__device__ float g_ln[BL*DM];

// ---------------- helpers ----------------------------------------------------
__device__ __forceinline__ uint32_t smem_u32(const void* p) {
    uint32_t a;
    asm("{ .reg .u64 t; cvta.to.shared.u64 t, %1; cvt.u32.u64 %0, t; }"
        : "=r"(a) : "l"(p));
    return a;
}
__device__ __forceinline__ uint32_t f2tf32(float x) {
    uint32_t u;
    asm("cvt.rna.tf32.f32 %0, %1;" : "=r"(u) : "f"(x));
    return u;
}
__device__ __forceinline__ void mma16n8k8(float* d, const uint32_t* a, const uint32_t* b) {
    asm volatile(
        "mma.sync.aligned.m16n8k8.row.col.f32.tf32.tf32.f32 "
        "{%0,%1,%2,%3}, {%4,%5,%6,%7}, {%8,%9}, {%0,%1,%2,%3};"
        : "+f"(d[0]), "+f"(d[1]), "+f"(d[2]), "+f"(d[3])
        : "r"(a[0]), "r"(a[1]), "r"(a[2]), "r"(a[3]), "r"(b[0]), "r"(b[1]));
}
__device__ __forceinline__ void cp16(uint32_t dst, const float* src, int srcsize) {
    asm volatile("cp.async.ca.shared.global [%0], [%1], 16, %2;"
                 :: "r"(dst), "l"(src), "r"(srcsize) : "memory");
}
#define CP_COMMIT()  asm volatile("cp.async.commit_group;" ::: "memory")
#define CP_WAIT(n)   asm volatile("cp.async.wait_group %0;" :: "n"(n) : "memory")

// ================== split-tf32 tensor-core GEMM: C = A @ W^T =================
// (R15 structure: STAGES-deep cp.async pipeline, one sync per K-iteration)
#define TSTR 20

template<int BMT, int NT, int STAGES>
__global__ __launch_bounds__(NT) void mma_gemm_t(
    const float* __restrict__ A, int lda,
    const float* __restrict__ W,
    const float* __restrict__ bias,
    const float* __restrict__ res,
    float* __restrict__ C,
    int N, int K, int act)
{
    constexpr int APT = BMT * 4 / NT;
    constexpr int BPT = 64 * 4 / NT;

    __shared__ float sA[STAGES][BMT*TSTR];
    __shared__ float sB[STAGES][64*TSTR];

    int tid = threadIdx.x;
    int wid = tid >> 5, lid = tid & 31;
    int warp_m = wid >> 1;
    int warp_n = wid & 1;
    int bm = blockIdx.y * BMT;
    int bn = blockIdx.x * 64;

    uint32_t aBase = smem_u32(&sA[0][0]);
    uint32_t bBase = smem_u32(&sB[0][0]);
    const uint32_t A_STAGE = BMT*TSTR*4;
    const uint32_t B_STAGE = 64*TSTR*4;

    int arr[APT], ac4[APT];
    #pragma unroll
    for (int j = 0; j < APT; j++) {
        int e = tid + j*NT;
        arr[j] = e >> 2; ac4[j] = (e & 3) * 4;
    }
    int brr[BPT], bc4[BPT], bpred[BPT];
    const float* bsrc[BPT];
    #pragma unroll
    for (int j = 0; j < BPT; j++) {
        int e = tid + j*NT;
        brr[j] = e >> 2; bc4[j] = (e & 3) * 4;
        int gn = bn + brr[j];
        bpred[j] = (gn < N) ? 16 : 0;
        bsrc[j] = W + (size_t)((gn < N) ? gn : 0) * K;
    }

    float acc[2][4][4];
    #pragma unroll
    for (int i = 0; i < 2; i++)
        #pragma unroll
        for (int j = 0; j < 4; j++)
            #pragma unroll
            for (int e = 0; e < 4; e++) acc[i][j][e] = 0.f;

    int nk = K >> 4;

    #pragma unroll
    for (int st = 0; st < STAGES-1; st++) {
        if (st < nk) {
            int k0 = st << 4;
            #pragma unroll
            for (int j = 0; j < APT; j++)
                cp16(aBase + (uint32_t)st*A_STAGE + (uint32_t)((arr[j]*TSTR + ac4[j])*4),
                     A + (size_t)(bm + arr[j])*lda + k0 + ac4[j], 16);
            #pragma unroll
            for (int j = 0; j < BPT; j++)
                cp16(bBase + (uint32_t)st*B_STAGE + (uint32_t)((brr[j]*TSTR + bc4[j])*4),
                     bsrc[j] + k0 + bc4[j], bpred[j]);
        }
        CP_COMMIT();
    }

    for (int kc = 0; kc < nk; kc++) {
        CP_WAIT(STAGES-2);
        __syncthreads();

        int nxt = kc + STAGES - 1;
        if (nxt < nk) {
            int k0 = nxt << 4;
            uint32_t so = (uint32_t)(nxt % STAGES);
            #pragma unroll
            for (int j = 0; j < APT; j++)
                cp16(aBase + so*A_STAGE + (uint32_t)((arr[j]*TSTR + ac4[j])*4),
                     A + (size_t)(bm + arr[j])*lda + k0 + ac4[j], 16);
            #pragma unroll
            for (int j = 0; j < BPT; j++)
                cp16(bBase + so*B_STAGE + (uint32_t)((brr[j]*TSTR + bc4[j])*4),
                     bsrc[j] + k0 + bc4[j], bpred[j]);
        }
        CP_COMMIT();

        const float* cA = sA[kc % STAGES];
        const float* cB = sB[kc % STAGES];

        #pragma unroll
        for (int ks = 0; ks < 2; ks++) {
            int kk = ks * 8;
            uint32_t ah[2][4], al[2][4];
            {
                int r0 = warp_m*32 + (lid >> 2);
                int c0 = kk + (lid & 3);
                #pragma unroll
                for (int im = 0; im < 2; im++) {
                    const float* pa = cA + (r0 + im*16)*TSTR + c0;
                    float f0 = pa[0], f1 = pa[8*TSTR], f2 = pa[4], f3 = pa[8*TSTR + 4];
                    ah[im][0] = f2tf32(f0); al[im][0] = f2tf32(f0 - __uint_as_float(ah[im][0]));
                    ah[im][1] = f2tf32(f1); al[im][1] = f2tf32(f1 - __uint_as_float(ah[im][1]));
                    ah[im][2] = f2tf32(f2); al[im][2] = f2tf32(f2 - __uint_as_float(ah[im][2]));
                    ah[im][3] = f2tf32(f3); al[im][3] = f2tf32(f3 - __uint_as_float(ah[im][3]));
                }
            }
            uint32_t bh[4][2], bl[4][2];
            {
                int n0 = warp_n*32 + (lid >> 2);
                int c0 = kk + (lid & 3);
                #pragma unroll
                for (int jn = 0; jn < 4; jn++) {
                    const float* pb = cB + (n0 + jn*8)*TSTR + c0;
                    float f0 = pb[0], f1 = pb[4];
                    bh[jn][0] = f2tf32(f0); bl[jn][0] = f2tf32(f0 - __uint_as_float(bh[jn][0]));
                    bh[jn][1] = f2tf32(f1); bl[jn][1] = f2tf32(f1 - __uint_as_float(bh[jn][1]));
                }
            }
            #pragma unroll
            for (int im = 0; im < 2; im++)
                #pragma unroll
                for (int jn = 0; jn < 4; jn++) {
                    mma16n8k8(acc[im][jn], ah[im], bh[jn]);
                    mma16n8k8(acc[im][jn], al[im], bh[jn]);
                    mma16n8k8(acc[im][jn], ah[im], bl[jn]);
                }
        }
    }

    // ---- epilogue ----
    int gm0 = bm + warp_m*32 + (lid >> 2);
    int gnb = bn + warp_n*32 + 2*(lid & 3);
    #pragma unroll
    for (int im = 0; im < 2; im++) {
        #pragma unroll
        for (int jn = 0; jn < 4; jn++) {
            int gn = gnb + jn*8;
            if (gn < N) {
                float b0 = 0.f, b1 = 0.f;
                if (bias) { b0 = bias[gn]; b1 = bias[gn+1]; }
                #pragma unroll
                for (int half = 0; half < 2; half++) {
                    int gm = gm0 + im*16 + half*8;
                    float v0 = acc[im][jn][half*2+0] + b0;
                    float v1 = acc[im][jn][half*2+1] + b1;
                    if (act == 1) {
                        v0 = (v0 > 15.f) ? v0 : log1pf(__expf(v0));
                        v1 = (v1 > 15.f) ? v1 : log1pf(__expf(v1));
                    }
                    if (res) {
                        float2 rv = *(const float2*)(res + (size_t)gm*N + gn);
                        v0 += rv.x; v1 += rv.y;
                    }
                    *(float2*)(C + (size_t)gm*N + gn) = make_float2(v0, v1);
                }
            }
        }
    }
}

// ---------------- depthwise causal conv (width 4) + SiLU --------------------
__global__ void conv_silu_kernel(const float* __restrict__ xz,
                                 const float* __restrict__ convw,
                                 const float* __restrict__ convb,
                                 float* __restrict__ u)
{
    int idx = blockIdx.x * blockDim.x + threadIdx.x;
    if (idx >= BL*DI) return;
    int d  = idx & (DI-1);
    int bt = idx >> 9;
    int t  = bt & (LL-1);

    float acc = convb[d];
    #pragma unroll
    for (int k = 0; k < DCONV; k++) {
        int tt = t - (DCONV-1) + k;
        if (tt >= 0)
            acc = fmaf(xz[(size_t)(bt - (DCONV-1) + k)*(2*DI) + d],
                       convw[d*DCONV + k], acc);
    }
    float sig = 1.f / (1.f + __expf(-acc));
    u[idx] = acc * sig;
}

// -------- tiled transpose: src[BL][DI] -> dst[DI][BL], 32x32 tiles ----------
// grid = (BL/32, DI/32, 2); z selects (u, delta). 256 threads = 32x8.
__global__ __launch_bounds__(256) void transpose_kernel(
    const float* __restrict__ src0, float* __restrict__ dst0,
    const float* __restrict__ src1, float* __restrict__ dst1)
{
    __shared__ float tile[32][33];
    const float* src = blockIdx.z ? src1 : src0;
    float* dst = blockIdx.z ? dst1 : dst0;

    int tbase = blockIdx.x * 32;   // t (row in src)
    int dbase = blockIdx.y * 32;   // d (col in src)
    int tx = threadIdx.x & 31;
    int ty = threadIdx.x >> 5;     // 0..7

    #pragma unroll
    for (int j = 0; j < 4; j++) {
        int r = ty + j*8;
        tile[r][tx] = src[(size_t)(tbase + r)*DI + dbase + tx];
    }
    __syncthreads();
    #pragma unroll
    for (int j = 0; j < 4; j++) {
        int r = ty + j*8;
        dst[(size_t)(dbase + r)*BL + tbase + tx] = tile[tx][r];
    }
}

// ====== chunked selective scan v6: smem-staged delta/u (coalesced loads) =====
__global__ __launch_bounds__(256) void scan6_kernel(
    const float* __restrict__ xz,
    const float* __restrict__ uT,       // [DI][BL]
    const float* __restrict__ dbc,      // [BL][48]
    const float* __restrict__ deltaT,   // [DI][BL]
    const float* __restrict__ a_log,
    const float* __restrict__ dparam,
    float* __restrict__ y_arr)
{
    __shared__ float s_delta[LL];
    __shared__ float s_u[LL];
    __shared__ float sC[16][17];
    __shared__ float sP[16][17];

    int bd = blockIdx.x;
    int d = bd & (DI-1), b = bd >> 9;
    int tid = threadIdx.x;
    int s = tid & 15, ck = tid >> 4;
    int t0 = ck * 128;
    int base = b * LL;

    // ---- stage A: coalesced float4 loads of delta/u rows ----
    const float* drow = deltaT + (size_t)d*BL + base;
    const float* urow = uT     + (size_t)d*BL + base;
    #pragma unroll
    for (int k = 0; k < 2; k++) {
        int f4 = tid + k*256;
        *(float4*)&s_delta[f4*4] = *(const float4*)(drow + f4*4);
        *(float4*)&s_u[f4*4]     = *(const float4*)(urow + f4*4);
    }
    __syncthreads();

    float A = -__expf(a_log[d*DS + s]);

    // ---- pass 1: chunk-local scan from h=0 (only Bt from global) ----
    float hloc = 0.f, sd = 0.f;
    #pragma unroll 4
    for (int i = 0; i < 128; i++) {
        int t = t0 + i;
        float delta = s_delta[t];
        float Bt    = dbc[(size_t)(base + t)*48 + DTR + s];
        float dA = __expf(delta * A);
        hloc = fmaf(dA, hloc, delta * s_u[t] * Bt);
        sd += delta;
    }
    sC[ck][s] = hloc;
    sP[ck][s] = __expf(sd * A);
    __syncthreads();

    // ---- prefix over chunks ----
    if (tid < 16) {
        float h = 0.f;
        #pragma unroll
        for (int c = 0; c < 16; c++) {
            float nh = fmaf(sP[c][tid], h, sC[c][tid]);
            sC[c][tid] = h;
            h = nh;
        }
    }
    __syncthreads();

    // ---- pass 2: rescan with true h_start, emit gated y ----
    float h = sC[ck][s];
    float Dp = dparam[d];
    #pragma unroll 4
    for (int i = 0; i < 128; i++) {
        int t = t0 + i;
        int row = base + t;
        float delta = s_delta[t];
        float uu    = s_u[t];
        float Bt    = dbc[(size_t)row*48 + DTR + s];
        float Ct    = dbc[(size_t)row*48 + DTR + DS + s];
        float dA = __expf(delta * A);
        h = fmaf(dA, h, delta * uu * Bt);

        float p = h * Ct;
        p += __shfl_xor_sync(0xffffffffu, p, 8);
        p += __shfl_xor_sync(0xffffffffu, p, 4);
        p += __shfl_xor_sync(0xffffffffu, p, 2);
        p += __shfl_xor_sync(0xffffffffu, p, 1);

        if (s == 0) {
            float z = xz[(size_t)row*(2*DI) + DI + d];
            float sig = 1.f / (1.f + __expf(-z));
            y_arr[(size_t)row*DI + d] = (p + uu * Dp) * (z * sig);
        }
    }
}

// ---------------- layernorm over 256 features (one warp per row) ------------
__global__ void ln_kernel(const float* __restrict__ x,
                          const float* __restrict__ w,
                          const float* __restrict__ b,
                          float* __restrict__ out)
{
    int warp = (blockIdx.x * blockDim.x + threadIdx.x) >> 5;
    int lane = threadIdx.x & 31;
    if (warp >= BL) return;
    const float* row = x + (size_t)warp*DM;

    float v[8];
    float sum = 0.f, sq = 0.f;
    #pragma unroll
    for (int k = 0; k < 8; k++) {
        v[k] = row[lane + k*32];
        sum += v[k];
        sq = fmaf(v[k], v[k], sq);
    }
    #pragma unroll
    for (int o = 16; o; o >>= 1) {
        sum += __shfl_xor_sync(0xffffffffu, sum, o);
        sq  += __shfl_xor_sync(0xffffffffu, sq,  o);
    }
    float mu  = sum * (1.f/DM);
    float var = sq * (1.f/DM) - mu*mu;
    float inv = rsqrtf(var + 1e-5f);
    #pragma unroll
    for (int k = 0; k < 8; k++) {
        int c = lane + k*32;
        out[(size_t)warp*DM + c] = (v[k]-mu)*inv*w[c] + b[c];
    }
}

// ---------------- host orchestration ----------------------------------------
static inline void launch_gemm_big(const float* A, int lda, const float* W,
                                   const float* bias, const float* res,
                                   float* C, int N, int K, int act)
{
    dim3 grid((N + 63) / 64, BL / 128);
    mma_gemm_t<128, 256, 3><<<grid, 256>>>(A, lda, W, bias, res, C, N, K, act);
}
static inline void launch_gemm_small(const float* A, int lda, const float* W,
                                     const float* bias, const float* res,
                                     float* C, int N, int K, int act)
{
    dim3 grid((N + 63) / 64, BL / 64);
    mma_gemm_t<64, 128, 4><<<grid, 128>>>(A, lda, W, bias, res, C, N, K, act);
}

extern "C" void kernel_launch(void* const* d_in, const int* in_sizes, int n_in,
                              void* d_out, int out_size)
{
    const float* x          = (const float*)d_in[0];
    const float* in_proj_w  = (const float*)d_in[1];
    const float* in_proj_b  = (const float*)d_in[2];
    const float* out_proj_w = (const float*)d_in[3];
    const float* out_proj_b = (const float*)d_in[4];
    const float* inw        = (const float*)d_in[5];
    const float* convw      = (const float*)d_in[6];
    const float* convb      = (const float*)d_in[7];
    const float* xpw        = (const float*)d_in[8];
    const float* dtw        = (const float*)d_in[9];
    const float* dtb        = (const float*)d_in[10];
    const float* a_log      = (const float*)d_in[11];
    const float* dparam     = (const float*)d_in[12];
    const float* outw       = (const float*)d_in[13];
    const float* lnw        = (const float*)d_in[14];
    const float* lnb        = (const float*)d_in[15];
    float* out = (float*)d_out;

    float *h, *xz, *u, *dbc, *delta, *uT, *deltaT, *y, *ln;
    cudaGetSymbolAddress((void**)&h,      g_h);
    cudaGetSymbolAddress((void**)&xz,     g_xz);
    cudaGetSymbolAddress((void**)&u,      g_u);
    cudaGetSymbolAddress((void**)&dbc,    g_dbc);
    cudaGetSymbolAddress((void**)&delta,  g_delta);
    cudaGetSymbolAddress((void**)&uT,     g_uT);
    cudaGetSymbolAddress((void**)&deltaT, g_deltaT);
    cudaGetSymbolAddress((void**)&y,      g_y);
    cudaGetSymbolAddress((void**)&ln,     g_ln);

    // h = x @ in_proj_w^T + in_proj_b
    launch_gemm_big(x, IN_DIM, in_proj_w, in_proj_b, nullptr, h, DM, IN_DIM, 0);

    for (int l = 0; l < NLAYERS; l++) {
        // xz = h @ inw[l]^T
        launch_gemm_big(h, DM, inw + (size_t)l*2*DI*DM, nullptr, nullptr, xz, 2*DI, DM, 0);
        // u = silu(causal_conv(xz[:, :DI]))
        conv_silu_kernel<<<(BL*DI)/256, 256>>>(xz, convw + l*DI*DCONV, convb + l*DI, u);
        // dbc = u @ xpw[l]^T   (N=48, small tile; verified faster)
        launch_gemm_small(u, DI, xpw + (size_t)l*48*DI, nullptr, nullptr, dbc, 48, DI, 0);
        // delta = softplus(dt @ dtw[l]^T + dtb[l])
        launch_gemm_big(dbc, 48, dtw + (size_t)l*DI*DTR, dtb + l*DI, nullptr, delta, DI, DTR, 1);
        // transpose u and delta -> [DI][BL] (coalesced both sides)
        transpose_kernel<<<dim3(BL/32, DI/32, 2), 256>>>(u, uT, delta, deltaT);
        // chunked selective scan + gating (smem-staged delta/u)
        scan6_kernel<<<BB*DI, 256>>>(xz, uT, dbc, deltaT,
                                     a_log + (size_t)l*DI*DS, dparam + l*DI, y);
        // ln_in = y @ outw[l]^T + residual(h)
        launch_gemm_big(y, DI, outw + (size_t)l*DM*DI, nullptr, h, ln, DM, DI, 0);
        // h = layernorm(ln_in)
        ln_kernel<<<BL/8, 256>>>(ln, lnw + l*DM, lnb + l*DM, h);
    }

    // out = h @ out_proj_w^T + out_proj_b
    launch_gemm_big(h, DM, out_proj_w, out_proj_b, nullptr, out, DM, DM, 0);
}

// round 17
// speedup vs baseline: 1.6151x; 1.1833x over previous
#include <cuda_runtime.h>
#include <math.h>
#include <stdint.h>

#define BB 4
#define LL 2048
#define IN_DIM 64
#define DM 256
#define DI 512
#define DS 16
#define DCONV 4
#define DTR 16
#define NLAYERS 4
#define BL (BB*LL)   // 8192 rows

// ---------------- scratch (static __device__, no allocation) ----------------
__device__ float g_h[BL*DM];
__device__ float g_xz[BL*2*DI];
__device__ float g_u[BL*DI];
__device__ float g_uT[(size_t)DI*BL];      // u transposed [d][t]
__device__ float g_dbc[BL*48];
__device__ float g_deltaT[(size_t)DI*BL];  // delta transposed [d][t]
__device__ float g_y[BL*DI];
__device__ float g_ln[BL*DM];

// ---------------- helpers ----------------------------------------------------
__device__ __forceinline__ uint32_t smem_u32(const void* p) {
    uint32_t a;
    asm("{ .reg .u64 t; cvta.to.shared.u64 t, %1; cvt.u32.u64 %0, t; }"
        : "=r"(a) : "l"(p));
    return a;
}
__device__ __forceinline__ uint32_t f2tf32(float x) {
    uint32_t u;
    asm("cvt.rna.tf32.f32 %0, %1;" : "=r"(u) : "f"(x));
    return u;
}
__device__ __forceinline__ void mma16n8k8(float* d, const uint32_t* a, const uint32_t* b) {
    asm volatile(
        "mma.sync.aligned.m16n8k8.row.col.f32.tf32.tf32.f32 "
        "{%0,%1,%2,%3}, {%4,%5,%6,%7}, {%8,%9}, {%0,%1,%2,%3};"
        : "+f"(d[0]), "+f"(d[1]), "+f"(d[2]), "+f"(d[3])
        : "r"(a[0]), "r"(a[1]), "r"(a[2]), "r"(a[3]), "r"(b[0]), "r"(b[1]));
}
__device__ __forceinline__ void cp16(uint32_t dst, const float* src, int srcsize) {
    asm volatile("cp.async.ca.shared.global [%0], [%1], 16, %2;"
                 :: "r"(dst), "l"(src), "r"(srcsize) : "memory");
}
#define CP_COMMIT()  asm volatile("cp.async.commit_group;" ::: "memory")
#define CP_WAIT(n)   asm volatile("cp.async.wait_group %0;" :: "n"(n) : "memory")

// ============ 2-term split-tf32 tensor-core GEMM: C = A @ W^T ================
// D = Ah*Bh + Ah*Bl  (A tf32-truncated; error ~2^-11 statistical)
// act: 0 = plain (+bias/res), 1 = softplus,
//      3 = softplus + TRANSPOSED store C[gn*BL+gm] (coalesced via smem staging)
#define TSTR 20

template<int BMT, int NT, int STAGES>
__global__ __launch_bounds__(NT) void mma_gemm_t(
    const float* __restrict__ A, int lda,
    const float* __restrict__ W,
    const float* __restrict__ bias,
    const float* __restrict__ res,
    float* __restrict__ C,
    int N, int K, int act)
{
    constexpr int APT = BMT * 4 / NT;
    constexpr int BPT = 64 * 4 / NT;
    constexpr int SA_SZ = STAGES * BMT * TSTR;
    constexpr int SB_SZ = STAGES * 64 * TSTR;

    __shared__ float sPool[SA_SZ + SB_SZ];
    float* sA = sPool;
    float* sB = sPool + SA_SZ;

    int tid = threadIdx.x;
    int wid = tid >> 5, lid = tid & 31;
    int warp_m = wid >> 1;
    int warp_n = wid & 1;
    int bm = blockIdx.y * BMT;
    int bn = blockIdx.x * 64;

    uint32_t aBase = smem_u32(sA);
    uint32_t bBase = smem_u32(sB);
    const uint32_t A_STAGE = BMT*TSTR*4;
    const uint32_t B_STAGE = 64*TSTR*4;

    int arr[APT], ac4[APT];
    #pragma unroll
    for (int j = 0; j < APT; j++) {
        int e = tid + j*NT;
        arr[j] = e >> 2; ac4[j] = (e & 3) * 4;
    }
    int brr[BPT], bc4[BPT], bpred[BPT];
    const float* bsrc[BPT];
    #pragma unroll
    for (int j = 0; j < BPT; j++) {
        int e = tid + j*NT;
        brr[j] = e >> 2; bc4[j] = (e & 3) * 4;
        int gn = bn + brr[j];
        bpred[j] = (gn < N) ? 16 : 0;
        bsrc[j] = W + (size_t)((gn < N) ? gn : 0) * K;
    }

    float acc[2][4][4];
    #pragma unroll
    for (int i = 0; i < 2; i++)
        #pragma unroll
        for (int j = 0; j < 4; j++)
            #pragma unroll
            for (int e = 0; e < 4; e++) acc[i][j][e] = 0.f;

    int nk = K >> 4;

    #pragma unroll
    for (int st = 0; st < STAGES-1; st++) {
        if (st < nk) {
            int k0 = st << 4;
            #pragma unroll
            for (int j = 0; j < APT; j++)
                cp16(aBase + (uint32_t)st*A_STAGE + (uint32_t)((arr[j]*TSTR + ac4[j])*4),
                     A + (size_t)(bm + arr[j])*lda + k0 + ac4[j], 16);
            #pragma unroll
            for (int j = 0; j < BPT; j++)
                cp16(bBase + (uint32_t)st*B_STAGE + (uint32_t)((brr[j]*TSTR + bc4[j])*4),
                     bsrc[j] + k0 + bc4[j], bpred[j]);
        }
        CP_COMMIT();
    }

    for (int kc = 0; kc < nk; kc++) {
        CP_WAIT(STAGES-2);
        __syncthreads();

        int nxt = kc + STAGES - 1;
        if (nxt < nk) {
            int k0 = nxt << 4;
            uint32_t so = (uint32_t)(nxt % STAGES);
            #pragma unroll
            for (int j = 0; j < APT; j++)
                cp16(aBase + so*A_STAGE + (uint32_t)((arr[j]*TSTR + ac4[j])*4),
                     A + (size_t)(bm + arr[j])*lda + k0 + ac4[j], 16);
            #pragma unroll
            for (int j = 0; j < BPT; j++)
                cp16(bBase + so*B_STAGE + (uint32_t)((brr[j]*TSTR + bc4[j])*4),
                     bsrc[j] + k0 + bc4[j], bpred[j]);
        }
        CP_COMMIT();

        const float* cA = sA + (kc % STAGES)*BMT*TSTR;
        const float* cB = sB + (kc % STAGES)*64*TSTR;

        #pragma unroll
        for (int ks = 0; ks < 2; ks++) {
            int kk = ks * 8;
            uint32_t ah[2][4];
            {
                int r0 = warp_m*32 + (lid >> 2);
                int c0 = kk + (lid & 3);
                #pragma unroll
                for (int im = 0; im < 2; im++) {
                    const float* pa = cA + (r0 + im*16)*TSTR + c0;
                    ah[im][0] = f2tf32(pa[0]);
                    ah[im][1] = f2tf32(pa[8*TSTR]);
                    ah[im][2] = f2tf32(pa[4]);
                    ah[im][3] = f2tf32(pa[8*TSTR + 4]);
                }
            }
            uint32_t bh[4][2], bl[4][2];
            {
                int n0 = warp_n*32 + (lid >> 2);
                int c0 = kk + (lid & 3);
                #pragma unroll
                for (int jn = 0; jn < 4; jn++) {
                    const float* pb = cB + (n0 + jn*8)*TSTR + c0;
                    float f0 = pb[0], f1 = pb[4];
                    bh[jn][0] = f2tf32(f0); bl[jn][0] = f2tf32(f0 - __uint_as_float(bh[jn][0]));
                    bh[jn][1] = f2tf32(f1); bl[jn][1] = f2tf32(f1 - __uint_as_float(bh[jn][1]));
                }
            }
            #pragma unroll
            for (int im = 0; im < 2; im++)
                #pragma unroll
                for (int jn = 0; jn < 4; jn++) {
                    mma16n8k8(acc[im][jn], ah[im], bh[jn]);
                    mma16n8k8(acc[im][jn], ah[im], bl[jn]);
                }
        }
    }

    // ---- epilogue ----
    int gm0 = bm + warp_m*32 + (lid >> 2);
    int gnb = bn + warp_n*32 + 2*(lid & 3);

    if (act == 3) {
        // softplus + transposed coalesced store via smem staging.
        // Requires 64*128 floats <= SA_SZ+SB_SZ (true for big-tile instance).
        float* st = sPool;
        __syncthreads();   // all mma reads of sPool done
        #pragma unroll
        for (int im = 0; im < 2; im++) {
            #pragma unroll
            for (int jn = 0; jn < 4; jn++) {
                int gn = gnb + jn*8;
                float b0 = 0.f, b1 = 0.f;
                if (bias) { b0 = bias[gn]; b1 = bias[gn+1]; }
                int ln0 = gn - bn;
                #pragma unroll
                for (int half = 0; half < 2; half++) {
                    int lm = (gm0 - bm) + im*16 + half*8;
                    float v0 = acc[im][jn][half*2+0] + b0;
                    float v1 = acc[im][jn][half*2+1] + b1;
                    v0 = (v0 > 15.f) ? v0 : log1pf(__expf(v0));
                    v1 = (v1 > 15.f) ? v1 : log1pf(__expf(v1));
                    st[ln0*128 + lm]     = v0;
                    st[(ln0+1)*128 + lm] = v1;
                }
            }
        }
        __syncthreads();
        for (int e = tid; e < 64*128; e += NT) {
            int ln = e >> 7, lm = e & 127;
            C[(size_t)(bn + ln)*BL + bm + lm] = st[e];
        }
        return;
    }

    #pragma unroll
    for (int im = 0; im < 2; im++) {
        #pragma unroll
        for (int jn = 0; jn < 4; jn++) {
            int gn = gnb + jn*8;
            if (gn < N) {
                float b0 = 0.f, b1 = 0.f;
                if (bias) { b0 = bias[gn]; b1 = bias[gn+1]; }
                #pragma unroll
                for (int half = 0; half < 2; half++) {
                    int gm = gm0 + im*16 + half*8;
                    float v0 = acc[im][jn][half*2+0] + b0;
                    float v1 = acc[im][jn][half*2+1] + b1;
                    if (act == 1) {
                        v0 = (v0 > 15.f) ? v0 : log1pf(__expf(v0));
                        v1 = (v1 > 15.f) ? v1 : log1pf(__expf(v1));
                    }
                    if (res) {
                        float2 rv = *(const float2*)(res + (size_t)gm*N + gn);
                        v0 += rv.x; v1 += rv.y;
                    }
                    *(float2*)(C + (size_t)gm*N + gn) = make_float2(v0, v1);
                }
            }
        }
    }
}

// ------- tiled depthwise conv + SiLU, emits u[t][d] AND uT[d][t] -------------
// grid (BL/32, DI/32), 256 threads (32 d-lanes x 8 t-rows).
__global__ __launch_bounds__(256) void conv_silu_t_kernel(
    const float* __restrict__ xz,
    const float* __restrict__ convw,
    const float* __restrict__ convb,
    float* __restrict__ u,
    float* __restrict__ uT)
{
    __shared__ float tile[32][33];
    int tbase = blockIdx.x * 32;
    int dbase = blockIdx.y * 32;
    int tx = threadIdx.x & 31;     // d offset
    int ty = threadIdx.x >> 5;     // 0..7
    int d = dbase + tx;

    float w0 = convw[d*DCONV + 0], w1 = convw[d*DCONV + 1];
    float w2 = convw[d*DCONV + 2], w3 = convw[d*DCONV + 3];
    float cb = convb[d];

    #pragma unroll
    for (int j = 0; j < 4; j++) {
        int trow = tbase + ty + j*8;       // global row in BL
        int t = trow & (LL-1);             // position within sequence
        float acc = cb;
        if (t >= 3) acc = fmaf(xz[(size_t)(trow-3)*(2*DI) + d], w0, acc);
        if (t >= 2) acc = fmaf(xz[(size_t)(trow-2)*(2*DI) + d], w1, acc);
        if (t >= 1) acc = fmaf(xz[(size_t)(trow-1)*(2*DI) + d], w2, acc);
        acc = fmaf(xz[(size_t)trow*(2*DI) + d], w3, acc);
        float sig = 1.f / (1.f + __expf(-acc));
        float val = acc * sig;
        u[(size_t)trow*DI + d] = val;
        tile[ty + j*8][tx] = val;
    }
    __syncthreads();
    #pragma unroll
    for (int j = 0; j < 4; j++) {
        int r = ty + j*8;                  // d-local
        uT[(size_t)(dbase + r)*BL + tbase + tx] = tile[tx][r];
    }
}

// ====== chunked selective scan v6: smem-staged delta/u (coalesced loads) =====
__global__ __launch_bounds__(256) void scan6_kernel(
    const float* __restrict__ xz,
    const float* __restrict__ uT,       // [DI][BL]
    const float* __restrict__ dbc,      // [BL][48]
    const float* __restrict__ deltaT,   // [DI][BL]
    const float* __restrict__ a_log,
    const float* __restrict__ dparam,
    float* __restrict__ y_arr)
{
    __shared__ float s_delta[LL];
    __shared__ float s_u[LL];
    __shared__ float sC[16][17];
    __shared__ float sP[16][17];

    int bd = blockIdx.x;
    int d = bd & (DI-1), b = bd >> 9;
    int tid = threadIdx.x;
    int s = tid & 15, ck = tid >> 4;
    int t0 = ck * 128;
    int base = b * LL;

    const float* drow = deltaT + (size_t)d*BL + base;
    const float* urow = uT     + (size_t)d*BL + base;
    #pragma unroll
    for (int k = 0; k < 2; k++) {
        int f4 = tid + k*256;
        *(float4*)&s_delta[f4*4] = *(const float4*)(drow + f4*4);
        *(float4*)&s_u[f4*4]     = *(const float4*)(urow + f4*4);
    }
    __syncthreads();

    float A = -__expf(a_log[d*DS + s]);

    float hloc = 0.f, sd = 0.f;
    #pragma unroll 4
    for (int i = 0; i < 128; i++) {
        int t = t0 + i;
        float delta = s_delta[t];
        float Bt    = dbc[(size_t)(base + t)*48 + DTR + s];
        float dA = __expf(delta * A);
        hloc = fmaf(dA, hloc, delta * s_u[t] * Bt);
        sd += delta;
    }
    sC[ck][s] = hloc;
    sP[ck][s] = __expf(sd * A);
    __syncthreads();

    if (tid < 16) {
        float h = 0.f;
        #pragma unroll
        for (int c = 0; c < 16; c++) {
            float nh = fmaf(sP[c][tid], h, sC[c][tid]);
            sC[c][tid] = h;
            h = nh;
        }
    }
    __syncthreads();

    float h = sC[ck][s];
    float Dp = dparam[d];
    #pragma unroll 4
    for (int i = 0; i < 128; i++) {
        int t = t0 + i;
        int row = base + t;
        float delta = s_delta[t];
        float uu    = s_u[t];
        float Bt    = dbc[(size_t)row*48 + DTR + s];
        float Ct    = dbc[(size_t)row*48 + DTR + DS + s];
        float dA = __expf(delta * A);
        h = fmaf(dA, h, delta * uu * Bt);

        float p = h * Ct;
        p += __shfl_xor_sync(0xffffffffu, p, 8);
        p += __shfl_xor_sync(0xffffffffu, p, 4);
        p += __shfl_xor_sync(0xffffffffu, p, 2);
        p += __shfl_xor_sync(0xffffffffu, p, 1);

        if (s == 0) {
            float z = xz[(size_t)row*(2*DI) + DI + d];
            float sig = 1.f / (1.f + __expf(-z));
            y_arr[(size_t)row*DI + d] = (p + uu * Dp) * (z * sig);
        }
    }
}

// ---------------- layernorm over 256 features (one warp per row) ------------
__global__ void ln_kernel(const float* __restrict__ x,
                          const float* __restrict__ w,
                          const float* __restrict__ b,
                          float* __restrict__ out)
{
    int warp = (blockIdx.x * blockDim.x + threadIdx.x) >> 5;
    int lane = threadIdx.x & 31;
    if (warp >= BL) return;
    const float* row = x + (size_t)warp*DM;

    float v[8];
    float sum = 0.f, sq = 0.f;
    #pragma unroll
    for (int k = 0; k < 8; k++) {
        v[k] = row[lane + k*32];
        sum += v[k];
        sq = fmaf(v[k], v[k], sq);
    }
    #pragma unroll
    for (int o = 16; o; o >>= 1) {
        sum += __shfl_xor_sync(0xffffffffu, sum, o);
        sq  += __shfl_xor_sync(0xffffffffu, sq,  o);
    }
    float mu  = sum * (1.f/DM);
    float var = sq * (1.f/DM) - mu*mu;
    float inv = rsqrtf(var + 1e-5f);
    #pragma unroll
    for (int k = 0; k < 8; k++) {
        int c = lane + k*32;
        out[(size_t)warp*DM + c] = (v[k]-mu)*inv*w[c] + b[c];
    }
}

// ---------------- host orchestration ----------------------------------------
static inline void launch_gemm_big(const float* A, int lda, const float* W,
                                   const float* bias, const float* res,
                                   float* C, int N, int K, int act)
{
    dim3 grid((N + 63) / 64, BL / 128);
    mma_gemm_t<128, 256, 3><<<grid, 256>>>(A, lda, W, bias, res, C, N, K, act);
}
static inline void launch_gemm_small(const float* A, int lda, const float* W,
                                     const float* bias, const float* res,
                                     float* C, int N, int K, int act)
{
    dim3 grid((N + 63) / 64, BL / 64);
    mma_gemm_t<64, 128, 4><<<grid, 128>>>(A, lda, W, bias, res, C, N, K, act);
}

extern "C" void kernel_launch(void* const* d_in, const int* in_sizes, int n_in,
                              void* d_out, int out_size)
{
    const float* x          = (const float*)d_in[0];
    const float* in_proj_w  = (const float*)d_in[1];
    const float* in_proj_b  = (const float*)d_in[2];
    const float* out_proj_w = (const float*)d_in[3];
    const float* out_proj_b = (const float*)d_in[4];
    const float* inw        = (const float*)d_in[5];
    const float* convw      = (const float*)d_in[6];
    const float* convb      = (const float*)d_in[7];
    const float* xpw        = (const float*)d_in[8];
    const float* dtw        = (const float*)d_in[9];
    const float* dtb        = (const float*)d_in[10];
    const float* a_log      = (const float*)d_in[11];
    const float* dparam     = (const float*)d_in[12];
    const float* outw       = (const float*)d_in[13];
    const float* lnw        = (const float*)d_in[14];
    const float* lnb        = (const float*)d_in[15];
    float* out = (float*)d_out;

    float *h, *xz, *u, *uT, *dbc, *deltaT, *y, *ln;
    cudaGetSymbolAddress((void**)&h,      g_h);
    cudaGetSymbolAddress((void**)&xz,     g_xz);
    cudaGetSymbolAddress((void**)&u,      g_u);
    cudaGetSymbolAddress((void**)&uT,     g_uT);
    cudaGetSymbolAddress((void**)&dbc,    g_dbc);
    cudaGetSymbolAddress((void**)&deltaT, g_deltaT);
    cudaGetSymbolAddress((void**)&y,      g_y);
    cudaGetSymbolAddress((void**)&ln,     g_ln);

    // h = x @ in_proj_w^T + in_proj_b
    launch_gemm_big(x, IN_DIM, in_proj_w, in_proj_b, nullptr, h, DM, IN_DIM, 0);

    for (int l = 0; l < NLAYERS; l++) {
        // xz = h @ inw[l]^T
        launch_gemm_big(h, DM, inw + (size_t)l*2*DI*DM, nullptr, nullptr, xz, 2*DI, DM, 0);
        // u = silu(causal_conv(xz[:, :DI]))  -> also uT (fused transpose)
        conv_silu_t_kernel<<<dim3(BL/32, DI/32), 256>>>(xz, convw + l*DI*DCONV,
                                                        convb + l*DI, u, uT);
        // dbc = u @ xpw[l]^T   (N=48, small tile; verified faster)
        launch_gemm_small(u, DI, xpw + (size_t)l*48*DI, nullptr, nullptr, dbc, 48, DI, 0);
        // deltaT = softplus(dt @ dtw[l]^T + dtb[l]) stored transposed (coalesced)
        launch_gemm_big(dbc, 48, dtw + (size_t)l*DI*DTR, dtb + l*DI, nullptr,
                        deltaT, DI, DTR, 3);
        // chunked selective scan + gating (smem-staged delta/u)
        scan6_kernel<<<BB*DI, 256>>>(xz, uT, dbc, deltaT,
                                     a_log + (size_t)l*DI*DS, dparam + l*DI, y);
        // ln_in = y @ outw[l]^T + residual(h)
        launch_gemm_big(y, DI, outw + (size_t)l*DM*DI, nullptr, h, ln, DM, DI, 0);
        // h = layernorm(ln_in)
        ln_kernel<<<BL/8, 256>>>(ln, lnw + l*DM, lnb + l*DM, h);
    }

    // out = h @ out_proj_w^T + out_proj_b
    launch_gemm_big(h, DM, out_proj_w, out_proj_b, nullptr, out, DM, DM, 0);
}